// round 11
// baseline (speedup 1.0000x reference)
#include <cuda_runtime.h>
#include <math.h>

#define NN 50000
#define FF 64
#define EE 1600000
#define HH 16
#define AA 8
#define NFIELD 8   /* 1 + RECEPTIVE_FIELD */
#define CAP 128    /* per-node CSR capacity; max in-degree ~60 for this graph */

// ---------------- static device scratch (no allocations allowed) ----------------
__device__ __align__(16) int   g_cursor[NN];
__device__ __align__(16) int   g_csr2[NN * CAP];      // 25.6 MB fixed-capacity CSR
__device__ __align__(16) float g_za[NN * HH];         // ping
__device__ __align__(16) float g_zb[NN * HH];         // pong
__device__ __align__(16) float g_r[NFIELD * NN * HH]; // relu2 hidden per field
__device__ __align__(16) float g_W31[HH * HH];        // w3 @ w1
__device__ __align__(16) float g_b31[HH];             // b3 @ w1
__device__ __align__(16) float g_T[NFIELD * FF * AA]; // fc1_w @ fc2_w
__device__ __align__(16) float g_G[NFIELD * HH * AA]; // w3 @ fc1_blk_i @ fc2_w
__device__ __align__(16) float g_bias[AA];            // folded logit bias
__device__ int g_is64;                                // edge dtype flag
__device__ int g_cnt;                                 // grid barrier counter (self-resetting)
__device__ volatile int g_flag;                       // grid barrier sense (toggles; any init ok)

// ---------------- software grid barrier (all blocks resident by construction) ----
__device__ __forceinline__ void gsync(int nb) {
    __syncthreads();
    if (threadIdx.x == 0) {
        int old = g_flag;
        __threadfence();
        if (atomicAdd(&g_cnt, 1) == nb - 1) {
            g_cnt = 0;
            __threadfence();
            g_flag = old ^ 1;
        } else {
            while (g_flag == old) { __nanosleep(64); }
        }
        __threadfence();
    }
    __syncthreads();
}

// ---------------- the single persistent kernel ----------------
__global__ void __launch_bounds__(256) k_main(
    const float* __restrict__ x,
    const int*   __restrict__ ei,     // edge_index words (int32 view; dtype detected)
    const float* __restrict__ w1, const float* __restrict__ b1,
    const float* __restrict__ w2, const float* __restrict__ b2,
    const float* __restrict__ w3, const float* __restrict__ b3,
    const float* __restrict__ fc1w, const float* __restrict__ fc1b,
    const float* __restrict__ fc2w, const float* __restrict__ fc2b,
    float* __restrict__ out, int G)
{
    __shared__ float s_w1[FF * HH];       // 4 KB
    __shared__ float s_w2[HH * HH];       // 1 KB
    __shared__ float s_W31[HH * HH];      // 1 KB
    __shared__ float s_G[NFIELD * HH * AA]; // 4 KB
    __shared__ float s_b1[HH], s_b2[HH], s_b31[HH], s_bias[AA];
    __shared__ float s_x[8][FF];          // 2 KB front staging
    __shared__ float s_z[8][HH];          // 512 B agg epilogue staging

    const int tid    = threadIdx.x;
    const int warp   = tid >> 5;
    const int lane   = tid & 31;
    const int gid    = blockIdx.x * 256 + tid;
    const int nthr   = G * 256;
    const int gwarp  = blockIdx.x * 8 + warp;
    const int nwarps = G * 8;

    // ================= P0: block 0 = folded weights + dtype detect; all = zero cursors
    if (blockIdx.x == 0) {
        int t = tid;
        // W31[k][j] = sum_f w3[k][f] * w1[f][j]   (256 entries, one per thread)
        {
            int k = t >> 4, j = t & 15;
            float s = 0.f;
            for (int f = 0; f < FF; f++) s += w3[k * FF + f] * w1[f * HH + j];
            g_W31[t] = s;
        }
        if (t < HH) {
            float s = 0.f;
            for (int f = 0; f < FF; f++) s += b3[f] * w1[f * HH + t];
            g_b31[t] = s;
        }
        // T[tt][a] = sum_k fc1w[tt][k] * fc2w[k][a], tt in [0,512)
        for (int tt = t; tt < NFIELD * FF; tt += 256) {
            float s[AA];
            #pragma unroll
            for (int a = 0; a < AA; a++) s[a] = 0.f;
            for (int k = 0; k < FF; k++) {
                float v = fc1w[tt * FF + k];
                #pragma unroll
                for (int a = 0; a < AA; a++) s[a] += v * fc2w[k * AA + a];
            }
            #pragma unroll
            for (int a = 0; a < AA; a++) g_T[tt * AA + a] = s[a];
        }
        __syncthreads();
        // G[i][j][a] = sum_f w3[j][f] * T[i*64+f][a]
        if (t < NFIELD * HH) {
            int i = t >> 4, j = t & 15;
            float s[AA];
            #pragma unroll
            for (int a = 0; a < AA; a++) s[a] = 0.f;
            for (int f = 0; f < FF; f++) {
                float v = w3[j * FF + f];
                #pragma unroll
                for (int a = 0; a < AA; a++) s[a] += v * g_T[(i * FF + f) * AA + a];
            }
            #pragma unroll
            for (int a = 0; a < AA; a++) g_G[t * AA + a] = s[a];
        }
        if (t < AA) {
            float s = fc2b[t];
            for (int k = 0; k < FF; k++) s += fc1b[k] * fc2w[k * AA + t];
            for (int q = 0; q < NFIELD * FF; q++) s += b3[q & (FF - 1)] * g_T[q * AA + t];
            g_bias[t] = s;
        }
        // dtype detect: sample 256 odd words across the 2*EE-word span.
        // int64 LE => high halves all zero; int32 => node ids (not all zero).
        long long si = (long long)t * (EE / 256);
        int nz = __syncthreads_or(ei[2 * si + 1] != 0);
        if (t == 0) g_is64 = (nz == 0);
    } else {
        // other blocks zero cursors (block 0's share handled by stride coverage below)
    }
    for (int i = gid; i < NN; i += nthr) g_cursor[i] = 0;

    gsync(G);

    // preload smem weights (g_W31/g_b31/g_G/g_bias now globally visible)
    for (int i = tid; i < FF * HH; i += 256) s_w1[i] = w1[i];
    if (tid < HH * HH) { s_w2[tid] = w2[tid]; s_W31[tid] = g_W31[tid]; }
    for (int i = tid; i < NFIELD * HH * AA; i += 256) s_G[i] = g_G[i];
    if (tid < HH) { s_b1[tid] = b1[tid]; s_b2[tid] = b2[tid]; s_b31[tid] = g_b31[tid]; }
    if (tid < AA) s_bias[tid] = g_bias[tid];
    const int is64 = g_is64;

    // ================= P1: CSR fill (fixed capacity, no hist/scan needed)
    for (int q = gid; q < EE / 4; q += nthr) {
        int s[4], d[4];
        if (!is64) {
            int4 s4 = *(const int4*)(ei + q * 4);
            int4 d4 = *(const int4*)(ei + EE + q * 4);
            s[0] = s4.x; s[1] = s4.y; s[2] = s4.z; s[3] = s4.w;
            d[0] = d4.x; d[1] = d4.y; d[2] = d4.z; d[3] = d4.w;
        } else {
            #pragma unroll
            for (int j = 0; j < 4; j++) {
                s[j] = ei[2 * (q * 4 + j)];
                d[j] = ei[2 * (long long)EE + 2 * (q * 4 + j)];
            }
        }
        #pragma unroll
        for (int j = 0; j < 4; j++) {
            if ((unsigned)d[j] < (unsigned)NN && (unsigned)s[j] < (unsigned)NN) {
                int p = atomicAdd(&g_cursor[d[j]], 1);
                if (p < CAP) g_csr2[d[j] * CAP + p] = s[j];
            }
        }
    }

    gsync(G);

    // ================= P2: front  x -> z0, relu2_0   (warp per node)
    for (int n = gwarp; n < NN; n += nwarps) {
        s_x[warp][lane]      = x[n * FF + lane];
        s_x[warp][lane + 32] = x[n * FF + lane + 32];
        __syncwarp();
        int j = lane & 15;
        float h1 = s_b1[j];
        #pragma unroll 16
        for (int f = 0; f < FF; f++) h1 += s_x[warp][f] * s_w1[f * HH + j];
        h1 = fmaxf(h1, 0.f);
        float h2 = s_b2[j];
        #pragma unroll
        for (int k = 0; k < HH; k++) h2 += __shfl_sync(0xffffffffu, h1, k) * s_w2[k * HH + j];
        h2 = fmaxf(h2, 0.f);
        float z = s_b31[j];
        #pragma unroll
        for (int k = 0; k < HH; k++) z += __shfl_sync(0xffffffffu, h2, k) * s_W31[k * HH + j];
        if (lane < HH) g_za[n * HH + j] = z;
        float h1b = fmaxf(z + s_b1[j], 0.f);
        float h2b = s_b2[j];
        #pragma unroll
        for (int k = 0; k < HH; k++) h2b += __shfl_sync(0xffffffffu, h1b, k) * s_w2[k * HH + j];
        h2b = fmaxf(h2b, 0.f);
        if (lane < HH) g_r[n * HH + j] = h2b;
        __syncwarp();
    }

    gsync(G);

    // ================= P3..P9: 7 aggregation passes
    for (int pass = 1; pass <= 7; pass++) {
        const float* zin  = (pass & 1) ? g_za : g_zb;
        float*       zout = (pass & 1) ? g_zb : g_za;
        float*       rout = g_r + (size_t)pass * (size_t)NN * HH;
        const int eg = lane >> 2;   // edge slot 0..7
        const int c4 = lane & 3;    // float4 column

        for (int n = gwarp; n < NN; n += nwarps) {
            int deg = g_cursor[n];
            const int* cp = g_csr2 + n * CAP;

            float4 acc = make_float4(0.f, 0.f, 0.f, 0.f);
            int noct = deg >> 3;
            int it = 0;
            for (; it + 2 <= noct; it += 2) {
                int s0 = cp[it * 8 + eg];
                int s1 = cp[it * 8 + 8 + eg];
                float4 v0 = *(const float4*)(zin + s0 * HH + c4 * 4);
                float4 v1 = *(const float4*)(zin + s1 * HH + c4 * 4);
                acc.x += v0.x + v1.x; acc.y += v0.y + v1.y;
                acc.z += v0.z + v1.z; acc.w += v0.w + v1.w;
            }
            for (; it < noct; it++) {
                int s = cp[it * 8 + eg];
                float4 v = *(const float4*)(zin + s * HH + c4 * 4);
                acc.x += v.x; acc.y += v.y; acc.z += v.z; acc.w += v.w;
            }
            int trem = deg & 7;
            if (eg < trem) {
                int s = cp[noct * 8 + eg];
                float4 v = *(const float4*)(zin + s * HH + c4 * 4);
                acc.x += v.x; acc.y += v.y; acc.z += v.z; acc.w += v.w;
            }
            #pragma unroll
            for (int off = 4; off < 32; off <<= 1) {
                acc.x += __shfl_xor_sync(0xffffffffu, acc.x, off);
                acc.y += __shfl_xor_sync(0xffffffffu, acc.y, off);
                acc.z += __shfl_xor_sync(0xffffffffu, acc.z, off);
                acc.w += __shfl_xor_sync(0xffffffffu, acc.w, off);
            }
            float inv = (deg > 0) ? 1.f / (float)deg : 0.f;
            acc.x *= inv; acc.y *= inv; acc.z *= inv; acc.w *= inv;

            if (lane < 4) {
                if (pass != 7) *(float4*)(zout + (size_t)n * HH + lane * 4) = acc;
                s_z[warp][lane * 4 + 0] = acc.x;
                s_z[warp][lane * 4 + 1] = acc.y;
                s_z[warp][lane * 4 + 2] = acc.z;
                s_z[warp][lane * 4 + 3] = acc.w;
            }
            __syncwarp();

            int f = lane & 15;
            float z = s_z[warp][f];
            float h1 = fmaxf(z + s_b1[f], 0.f);
            float h2 = s_b2[f];
            #pragma unroll
            for (int k = 0; k < HH; k++) h2 += __shfl_sync(0xffffffffu, h1, k) * s_w2[k * HH + f];
            h2 = fmaxf(h2, 0.f);
            if (lane < HH) rout[(size_t)n * HH + f] = h2;
            __syncwarp();
        }
        gsync(G);
    }

    // ================= P10: final head + softmax (thread per node)
    for (int n = gid; n < NN; n += nthr) {
        float acc[AA];
        #pragma unroll
        for (int a = 0; a < AA; a++) acc[a] = s_bias[a];

        #pragma unroll
        for (int i = 0; i < NFIELD; i++) {
            const float4* rp = (const float4*)(g_r + (size_t)i * (size_t)NN * HH + (size_t)n * HH);
            float4 q0 = rp[0], q1 = rp[1], q2 = rp[2], q3 = rp[3];
            float rv[16] = {q0.x, q0.y, q0.z, q0.w, q1.x, q1.y, q1.z, q1.w,
                            q2.x, q2.y, q2.z, q2.w, q3.x, q3.y, q3.z, q3.w};
            const float* Gp = s_G + i * HH * AA;
            #pragma unroll
            for (int jj = 0; jj < HH; jj++) {
                float r = rv[jj];
                #pragma unroll
                for (int a = 0; a < AA; a++) acc[a] += r * Gp[jj * AA + a];
            }
        }

        float mx = acc[0];
        #pragma unroll
        for (int a = 1; a < AA; a++) mx = fmaxf(mx, acc[a]);
        float sum = 0.f;
        #pragma unroll
        for (int a = 0; a < AA; a++) { acc[a] = __expf(acc[a] - mx); sum += acc[a]; }
        float inv = 1.f / sum;
        #pragma unroll
        for (int a = 0; a < AA; a++) out[(size_t)n * AA + a] = acc[a] * inv;
    }
}

// ---------------- launch: one kernel, grid = exact resident capacity ----------------
extern "C" void kernel_launch(void* const* d_in, const int* in_sizes, int n_in,
                              void* d_out, int out_size) {
    const float* x    = (const float*)d_in[0];
    const int*   ei   = (const int*)d_in[1];
    const float* w1   = (const float*)d_in[2];
    const float* b1   = (const float*)d_in[3];
    const float* w2   = (const float*)d_in[4];
    const float* b2   = (const float*)d_in[5];
    const float* w3   = (const float*)d_in[6];
    const float* b3   = (const float*)d_in[7];
    const float* fc1w = (const float*)d_in[8];
    const float* fc1b = (const float*)d_in[9];
    const float* fc2w = (const float*)d_in[10];
    const float* fc2b = (const float*)d_in[11];
    float* out = (float*)d_out;

    int dev = 0;
    cudaGetDevice(&dev);
    cudaDeviceProp prop;
    cudaGetDeviceProperties(&prop, dev);
    int nb = 0;
    cudaOccupancyMaxActiveBlocksPerMultiprocessor(&nb, k_main, 256, 0);
    if (nb < 1) nb = 1;
    long long Gl = (long long)nb * prop.multiProcessorCount;
    if (Gl > 2048) Gl = 2048;
    int G = (int)Gl;

    k_main<<<G, 256>>>(x, ei, w1, b1, w2, b2, w3, b3,
                       fc1w, fc1b, fc2w, fc2b, out, G);
}

// round 12
// speedup vs baseline: 1.1651x; 1.1651x over previous
#include <cuda_runtime.h>
#include <math.h>

#define NN 50000
#define FF 64
#define EE 1600000
#define HH 16
#define AA 8
#define NFIELD 8   /* 1 + RECEPTIVE_FIELD */
#define CAP 128    /* per-node CSR capacity; max in-degree ~60 for this graph */

// ---------------- static device scratch (no allocations allowed) ----------------
__device__ __align__(16) int   g_cursor[NN];
__device__ __align__(16) int   g_csr2[NN * CAP];      // fixed-capacity CSR
__device__ __align__(16) float g_za[NN * HH];         // ping
__device__ __align__(16) float g_zb[NN * HH];         // pong
__device__ __align__(16) float g_r[NFIELD * NN * HH]; // relu2 hidden per field
__device__ __align__(16) float g_W31[HH * HH];        // w3 @ w1
__device__ __align__(16) float g_b31[HH];             // b3 @ w1
__device__ __align__(16) float g_T[NFIELD * FF * AA]; // fc1_w @ fc2_w
__device__ __align__(16) float g_G[NFIELD * HH * AA]; // w3 @ fc1_blk_i @ fc2_w
__device__ __align__(16) float g_bias[AA];            // folded logit bias
__device__ int g_is64;                                // edge dtype flag
__device__ int g_cnt;                                 // grid barrier counter (self-resetting)
__device__ volatile int g_flag;                       // grid barrier sense

// ---------------- software grid barrier (all blocks resident by construction) ----
__device__ __forceinline__ void gsync(int nb) {
    __syncthreads();
    if (threadIdx.x == 0) {
        int old = g_flag;
        __threadfence();
        if (atomicAdd(&g_cnt, 1) == nb - 1) {
            g_cnt = 0;
            __threadfence();
            g_flag = old ^ 1;
        } else {
            while (g_flag == old) { __nanosleep(64); }
        }
        __threadfence();
    }
    __syncthreads();
}

// ---------------- the single persistent kernel (reg-capped for occupancy) -------
__global__ void __launch_bounds__(256, 6) k_main(
    const float* __restrict__ x,
    const int*   __restrict__ ei,
    const float* __restrict__ w1, const float* __restrict__ b1,
    const float* __restrict__ w2, const float* __restrict__ b2,
    const float* __restrict__ w3, const float* __restrict__ b3,
    const float* __restrict__ fc1w, const float* __restrict__ fc1b,
    const float* __restrict__ fc2w, const float* __restrict__ fc2b,
    float* __restrict__ out, int G)
{
    __shared__ float s_w1[FF * HH];
    __shared__ float s_w2[HH * HH];
    __shared__ float s_W31[HH * HH];
    __shared__ float s_G[NFIELD * HH * AA];
    __shared__ float s_b1[HH], s_b2[HH], s_b31[HH], s_bias[AA];
    __shared__ float s_x[8][FF];
    __shared__ float s_z[8][HH];

    const int tid    = threadIdx.x;
    const int warp   = tid >> 5;
    const int lane   = tid & 31;
    const int gid    = blockIdx.x * 256 + tid;
    const int nthr   = G * 256;
    const int gwarp  = blockIdx.x * 8 + warp;
    const int nwarps = G * 8;

    // ===== P0: block 0 folds weights + detects dtype; everyone zeros cursors
    if (blockIdx.x == 0) {
        int t = tid;
        {
            int k = t >> 4, j = t & 15;
            float s = 0.f;
            for (int f = 0; f < FF; f++) s += w3[k * FF + f] * w1[f * HH + j];
            g_W31[t] = s;
        }
        if (t < HH) {
            float s = 0.f;
            for (int f = 0; f < FF; f++) s += b3[f] * w1[f * HH + t];
            g_b31[t] = s;
        }
        for (int tt = t; tt < NFIELD * FF; tt += 256) {
            float s[AA];
            #pragma unroll
            for (int a = 0; a < AA; a++) s[a] = 0.f;
            for (int k = 0; k < FF; k++) {
                float v = fc1w[tt * FF + k];
                #pragma unroll
                for (int a = 0; a < AA; a++) s[a] += v * fc2w[k * AA + a];
            }
            #pragma unroll
            for (int a = 0; a < AA; a++) g_T[tt * AA + a] = s[a];
        }
        __syncthreads();
        if (t < NFIELD * HH) {
            int i = t >> 4, j = t & 15;
            float s[AA];
            #pragma unroll
            for (int a = 0; a < AA; a++) s[a] = 0.f;
            for (int f = 0; f < FF; f++) {
                float v = w3[j * FF + f];
                #pragma unroll
                for (int a = 0; a < AA; a++) s[a] += v * g_T[(i * FF + f) * AA + a];
            }
            #pragma unroll
            for (int a = 0; a < AA; a++) g_G[t * AA + a] = s[a];
        }
        if (t < AA) {
            float s = fc2b[t];
            for (int k = 0; k < FF; k++) s += fc1b[k] * fc2w[k * AA + t];
            for (int q = 0; q < NFIELD * FF; q++) s += b3[q & (FF - 1)] * g_T[q * AA + t];
            g_bias[t] = s;
        }
        long long si = (long long)t * (EE / 256);
        int nz = __syncthreads_or(ei[2 * si + 1] != 0);
        if (t == 0) g_is64 = (nz == 0);
    }
    for (int i = gid; i < NN; i += nthr) g_cursor[i] = 0;

    gsync(G);

    // preload smem weights
    for (int i = tid; i < FF * HH; i += 256) s_w1[i] = w1[i];
    if (tid < HH * HH) { s_w2[tid] = w2[tid]; s_W31[tid] = g_W31[tid]; }
    for (int i = tid; i < NFIELD * HH * AA; i += 256) s_G[i] = g_G[i];
    if (tid < HH) { s_b1[tid] = b1[tid]; s_b2[tid] = b2[tid]; s_b31[tid] = g_b31[tid]; }
    if (tid < AA) s_bias[tid] = g_bias[tid];
    const int is64 = g_is64;

    // ===== P1: CSR fill AND front (independent; one phase)
    for (int q = gid; q < EE / 4; q += nthr) {
        int s[4], d[4];
        if (!is64) {
            int4 s4 = *(const int4*)(ei + q * 4);
            int4 d4 = *(const int4*)(ei + EE + q * 4);
            s[0] = s4.x; s[1] = s4.y; s[2] = s4.z; s[3] = s4.w;
            d[0] = d4.x; d[1] = d4.y; d[2] = d4.z; d[3] = d4.w;
        } else {
            #pragma unroll
            for (int j = 0; j < 4; j++) {
                s[j] = ei[2 * (q * 4 + j)];
                d[j] = ei[2 * (long long)EE + 2 * (q * 4 + j)];
            }
        }
        #pragma unroll
        for (int j = 0; j < 4; j++) {
            if ((unsigned)d[j] < (unsigned)NN && (unsigned)s[j] < (unsigned)NN) {
                int p = atomicAdd(&g_cursor[d[j]], 1);
                if (p < CAP) g_csr2[d[j] * CAP + p] = s[j];
            }
        }
    }
    // front: x -> z0, relu2_0 (warp per node)
    for (int n = gwarp; n < NN; n += nwarps) {
        s_x[warp][lane]      = x[n * FF + lane];
        s_x[warp][lane + 32] = x[n * FF + lane + 32];
        __syncwarp();
        int j = lane & 15;
        float h1 = s_b1[j];
        #pragma unroll 16
        for (int f = 0; f < FF; f++) h1 += s_x[warp][f] * s_w1[f * HH + j];
        h1 = fmaxf(h1, 0.f);
        float h2 = s_b2[j];
        #pragma unroll
        for (int k = 0; k < HH; k++) h2 += __shfl_sync(0xffffffffu, h1, k) * s_w2[k * HH + j];
        h2 = fmaxf(h2, 0.f);
        float z = s_b31[j];
        #pragma unroll
        for (int k = 0; k < HH; k++) z += __shfl_sync(0xffffffffu, h2, k) * s_W31[k * HH + j];
        if (lane < HH) g_za[n * HH + j] = z;
        float h1b = fmaxf(z + s_b1[j], 0.f);
        float h2b = s_b2[j];
        #pragma unroll
        for (int k = 0; k < HH; k++) h2b += __shfl_sync(0xffffffffu, h1b, k) * s_w2[k * HH + j];
        h2b = fmaxf(h2b, 0.f);
        if (lane < HH) g_r[n * HH + j] = h2b;
        __syncwarp();
    }

    gsync(G);

    // ===== P2..P8: 7 aggregation passes
    for (int pass = 1; pass <= 7; pass++) {
        const float* zin  = (pass & 1) ? g_za : g_zb;
        float*       zout = (pass & 1) ? g_zb : g_za;
        float*       rout = g_r + (size_t)pass * (size_t)NN * HH;
        const int eg = lane >> 2;
        const int c4 = lane & 3;

        for (int n = gwarp; n < NN; n += nwarps) {
            int deg = g_cursor[n];
            const int* cp = g_csr2 + n * CAP;

            float4 acc = make_float4(0.f, 0.f, 0.f, 0.f);
            int noct = deg >> 3;
            int it = 0;
            for (; it + 2 <= noct; it += 2) {
                int s0 = cp[it * 8 + eg];
                int s1 = cp[it * 8 + 8 + eg];
                float4 v0 = *(const float4*)(zin + s0 * HH + c4 * 4);
                float4 v1 = *(const float4*)(zin + s1 * HH + c4 * 4);
                acc.x += v0.x + v1.x; acc.y += v0.y + v1.y;
                acc.z += v0.z + v1.z; acc.w += v0.w + v1.w;
            }
            for (; it < noct; it++) {
                int s = cp[it * 8 + eg];
                float4 v = *(const float4*)(zin + s * HH + c4 * 4);
                acc.x += v.x; acc.y += v.y; acc.z += v.z; acc.w += v.w;
            }
            int trem = deg & 7;
            if (eg < trem) {
                int s = cp[noct * 8 + eg];
                float4 v = *(const float4*)(zin + s * HH + c4 * 4);
                acc.x += v.x; acc.y += v.y; acc.z += v.z; acc.w += v.w;
            }
            #pragma unroll
            for (int off = 4; off < 32; off <<= 1) {
                acc.x += __shfl_xor_sync(0xffffffffu, acc.x, off);
                acc.y += __shfl_xor_sync(0xffffffffu, acc.y, off);
                acc.z += __shfl_xor_sync(0xffffffffu, acc.z, off);
                acc.w += __shfl_xor_sync(0xffffffffu, acc.w, off);
            }
            float inv = (deg > 0) ? 1.f / (float)deg : 0.f;
            acc.x *= inv; acc.y *= inv; acc.z *= inv; acc.w *= inv;

            if (lane < 4) {
                if (pass != 7) *(float4*)(zout + (size_t)n * HH + lane * 4) = acc;
                s_z[warp][lane * 4 + 0] = acc.x;
                s_z[warp][lane * 4 + 1] = acc.y;
                s_z[warp][lane * 4 + 2] = acc.z;
                s_z[warp][lane * 4 + 3] = acc.w;
            }
            __syncwarp();

            int f = lane & 15;
            float z = s_z[warp][f];
            float h1 = fmaxf(z + s_b1[f], 0.f);
            float h2 = s_b2[f];
            #pragma unroll
            for (int k = 0; k < HH; k++) h2 += __shfl_sync(0xffffffffu, h1, k) * s_w2[k * HH + f];
            h2 = fmaxf(h2, 0.f);
            if (lane < HH) rout[(size_t)n * HH + f] = h2;
            __syncwarp();
        }
        gsync(G);
    }

    // ===== P9: final head + softmax (thread per node)
    for (int n = gid; n < NN; n += nthr) {
        float acc[AA];
        #pragma unroll
        for (int a = 0; a < AA; a++) acc[a] = s_bias[a];

        #pragma unroll
        for (int i = 0; i < NFIELD; i++) {
            const float4* rp = (const float4*)(g_r + (size_t)i * (size_t)NN * HH + (size_t)n * HH);
            const float* Gp = s_G + i * HH * AA;
            #pragma unroll
            for (int v4 = 0; v4 < 4; v4++) {
                float4 q = rp[v4];
                const float* Gq = Gp + v4 * 4 * AA;
                #pragma unroll
                for (int a = 0; a < AA; a++)
                    acc[a] += q.x * Gq[0 * AA + a] + q.y * Gq[1 * AA + a]
                            + q.z * Gq[2 * AA + a] + q.w * Gq[3 * AA + a];
            }
        }

        float mx = acc[0];
        #pragma unroll
        for (int a = 1; a < AA; a++) mx = fmaxf(mx, acc[a]);
        float sum = 0.f;
        #pragma unroll
        for (int a = 0; a < AA; a++) { acc[a] = __expf(acc[a] - mx); sum += acc[a]; }
        float inv = 1.f / sum;
        #pragma unroll
        for (int a = 0; a < AA; a++) out[(size_t)n * AA + a] = acc[a] * inv;
    }
}

// ---------------- launch ----------------
extern "C" void kernel_launch(void* const* d_in, const int* in_sizes, int n_in,
                              void* d_out, int out_size) {
    const float* x    = (const float*)d_in[0];
    const int*   ei   = (const int*)d_in[1];
    const float* w1   = (const float*)d_in[2];
    const float* b1   = (const float*)d_in[3];
    const float* w2   = (const float*)d_in[4];
    const float* b2   = (const float*)d_in[5];
    const float* w3   = (const float*)d_in[6];
    const float* b3   = (const float*)d_in[7];
    const float* fc1w = (const float*)d_in[8];
    const float* fc1b = (const float*)d_in[9];
    const float* fc2w = (const float*)d_in[10];
    const float* fc2b = (const float*)d_in[11];
    float* out = (float*)d_out;

    int dev = 0;
    cudaGetDevice(&dev);
    cudaDeviceProp prop;
    cudaGetDeviceProperties(&prop, dev);
    int nb = 0;
    cudaOccupancyMaxActiveBlocksPerMultiprocessor(&nb, k_main, 256, 0);
    if (nb < 1) nb = 1;
    long long Gl = (long long)nb * prop.multiProcessorCount;
    if (Gl > 4096) Gl = 4096;
    int G = (int)Gl;

    k_main<<<G, 256>>>(x, ei, w1, b1, w2, b2, w3, b3,
                       fc1w, fc1b, fc2w, fc2b, out, G);
}

// round 14
// speedup vs baseline: 1.1938x; 1.0246x over previous
#include <cuda_runtime.h>
#include <cuda_fp16.h>
#include <math.h>

#define NN 50000
#define FF 64
#define EE 1600000
#define HH 16
#define AA 8
#define NFIELD 8   /* 1 + RECEPTIVE_FIELD */
#define CAP 128    /* per-node CSR capacity; max in-degree ~60 for this graph */

// ---------------- static device scratch ----------------
__device__ __align__(16) int    g_cursor[NN];
__device__ __align__(16) int    g_csr2[NN * CAP];       // fixed-capacity CSR (cursor = degree)
__device__ __align__(16) __half g_zha[NN * HH];         // ping (fp16 propagated features)
__device__ __align__(16) __half g_zhb[NN * HH];         // pong
__device__ __align__(16) float  g_r[NFIELD * NN * HH];  // relu2 hidden per field (fp32)
__device__ __align__(16) float  g_W31[HH * HH];         // w3 @ w1
__device__ __align__(16) float  g_b31[HH];              // b3 @ w1
__device__ __align__(16) float  g_T[NFIELD * FF * AA];  // fc1_w @ fc2_w
__device__ __align__(16) float  g_G[NFIELD * HH * AA];  // w3 @ fc1_blk_i @ fc2_w
__device__ __align__(16) float  g_bias[AA];             // folded logit bias
__device__ int g_odd_nonzero;                           // dtype detection scratch

// ---------------- half2 <-> uint bit-casts ----------------
__device__ __forceinline__ unsigned pack_h2(float a, float b) {
    __half2 h = __floats2half2_rn(a, b);
    return *reinterpret_cast<unsigned*>(&h);
}
__device__ __forceinline__ float2 unpack_h2(unsigned v) {
    __half2 h = *reinterpret_cast<__half2*>(&v);
    return __half22float2(h);
}

// ---------------- folded weights precompute ----------------
__global__ void k_pre(const float* __restrict__ w1, const float* __restrict__ b1,
                      const float* __restrict__ w3, const float* __restrict__ b3,
                      const float* __restrict__ fc1w, const float* __restrict__ fc1b,
                      const float* __restrict__ fc2w, const float* __restrict__ fc2b) {
    int t = threadIdx.x;  // 512 threads, 1 block
    if (t < HH * HH) {
        int k = t >> 4, j = t & 15;
        float s = 0.f;
        for (int f = 0; f < FF; f++) s += w3[k * FF + f] * w1[f * HH + j];
        g_W31[t] = s;
    }
    if (t < HH) {
        float s = 0.f;
        for (int f = 0; f < FF; f++) s += b3[f] * w1[f * HH + t];
        g_b31[t] = s;
    }
    {
        float s[AA];
        #pragma unroll
        for (int a = 0; a < AA; a++) s[a] = 0.f;
        for (int k = 0; k < FF; k++) {
            float v = fc1w[t * FF + k];
            #pragma unroll
            for (int a = 0; a < AA; a++) s[a] += v * fc2w[k * AA + a];
        }
        #pragma unroll
        for (int a = 0; a < AA; a++) g_T[t * AA + a] = s[a];
    }
    __syncthreads();
    if (t < NFIELD * HH) {
        int i = t >> 4, j = t & 15;
        float s[AA];
        #pragma unroll
        for (int a = 0; a < AA; a++) s[a] = 0.f;
        for (int f = 0; f < FF; f++) {
            float v = w3[j * FF + f];
            #pragma unroll
            for (int a = 0; a < AA; a++) s[a] += v * g_T[(i * FF + f) * AA + a];
        }
        #pragma unroll
        for (int a = 0; a < AA; a++) g_G[t * AA + a] = s[a];
    }
    if (t < AA) {
        float s = fc2b[t];
        for (int k = 0; k < FF; k++) s += fc1b[k] * fc2w[k * AA + t];
        for (int q = 0; q < NFIELD * FF; q++) s += b3[q & (FF - 1)] * g_T[q * AA + t];
        g_bias[t] = s;
    }
}

// ---------------- CSR build (no hist/scan: fixed-capacity rows) ----------------
__global__ void k_zero() {
    int i = blockIdx.x * 256 + threadIdx.x;
    if (i < NN) g_cursor[i] = 0;
    if (i == 0) g_odd_nonzero = 0;
}

__global__ void k_detect(const int* __restrict__ w) {
    int t = blockIdx.x * 256 + threadIdx.x;   // 4096 threads
    long long i = (long long)t * (EE / 4096);
    if (w[2 * i + 1] != 0) atomicOr(&g_odd_nonzero, 1);
}

__global__ void k_fill(const int* __restrict__ w) {
    int q = blockIdx.x * 256 + threadIdx.x;
    if (q >= EE / 4) return;
    int is64 = (g_odd_nonzero == 0);
    int s[4], d[4];
    if (!is64) {
        int4 s4 = *(const int4*)(w + q * 4);
        int4 d4 = *(const int4*)(w + EE + q * 4);
        s[0] = s4.x; s[1] = s4.y; s[2] = s4.z; s[3] = s4.w;
        d[0] = d4.x; d[1] = d4.y; d[2] = d4.z; d[3] = d4.w;
    } else {
        #pragma unroll
        for (int j = 0; j < 4; j++) {
            s[j] = w[2 * (q * 4 + j)];
            d[j] = w[2 * (long long)EE + 2 * (q * 4 + j)];
        }
    }
    #pragma unroll
    for (int j = 0; j < 4; j++) {
        if ((unsigned)d[j] < (unsigned)NN && (unsigned)s[j] < (unsigned)NN) {
            int p = atomicAdd(&g_cursor[d[j]], 1);
            if (p < CAP) g_csr2[d[j] * CAP + p] = s[j];
        }
    }
}

// helper: store 8 floats as 8 halves (16B store)
__device__ __forceinline__ void store_half8(__half* dst, const float* v) {
    uint4 u;
    u.x = pack_h2(v[0], v[1]);
    u.y = pack_h2(v[2], v[3]);
    u.z = pack_h2(v[4], v[5]);
    u.w = pack_h2(v[6], v[7]);
    *(uint4*)dst = u;
}

// ---------------- front: x -> z0 (stored fp16), relu2_0 (exact fp32) ----------------
__global__ void __launch_bounds__(256) k_front(const float* __restrict__ x,
                                               const float* __restrict__ w1, const float* __restrict__ b1,
                                               const float* __restrict__ w2, const float* __restrict__ b2) {
    __shared__ float s_w1[FF * HH];
    __shared__ float s_w2[HH * HH];
    __shared__ float s_W31[HH * HH];
    __shared__ float s_b1[HH], s_b2[HH], s_b31[HH];
    __shared__ float s_x[8][FF];
    __shared__ float s_zz[8][HH];
    int tid = threadIdx.x;
    for (int i = tid; i < FF * HH; i += 256) s_w1[i] = w1[i];
    if (tid < HH * HH) { s_w2[tid] = w2[tid]; s_W31[tid] = g_W31[tid]; }
    if (tid < HH) { s_b1[tid] = b1[tid]; s_b2[tid] = b2[tid]; s_b31[tid] = g_b31[tid]; }
    __syncthreads();
    int warp = tid >> 5, lane = tid & 31;
    int n = blockIdx.x * 8 + warp;   // grid = NN/8 exactly

    s_x[warp][lane]      = x[n * FF + lane];
    s_x[warp][lane + 32] = x[n * FF + lane + 32];
    __syncwarp();

    int j = lane & 15;
    float h1 = s_b1[j];
    #pragma unroll 16
    for (int f = 0; f < FF; f++) h1 += s_x[warp][f] * s_w1[f * HH + j];
    h1 = fmaxf(h1, 0.f);
    float h2 = s_b2[j];
    #pragma unroll
    for (int k = 0; k < HH; k++) h2 += __shfl_sync(0xffffffffu, h1, k) * s_w2[k * HH + j];
    h2 = fmaxf(h2, 0.f);
    float z = s_b31[j];
    #pragma unroll
    for (int k = 0; k < HH; k++) z += __shfl_sync(0xffffffffu, h2, k) * s_W31[k * HH + j];
    if (lane < HH) s_zz[warp][j] = z;
    __syncwarp();
    if (lane < 2) store_half8(g_zha + (size_t)n * HH + lane * 8, &s_zz[warp][lane * 8]);

    float h1b = fmaxf(z + s_b1[j], 0.f);
    float h2b = s_b2[j];
    #pragma unroll
    for (int k = 0; k < HH; k++) h2b += __shfl_sync(0xffffffffu, h1b, k) * s_w2[k * HH + j];
    h2b = fmaxf(h2b, 0.f);
    if (lane < HH) g_r[n * HH + j] = h2b;
}

// ---------------- agg: 16 edges/warp-iter via 16B half-row loads, fused relu2 ------
__global__ void __launch_bounds__(256) k_agg(int pass,
                                             const float* __restrict__ b1,
                                             const float* __restrict__ w2,
                                             const float* __restrict__ b2) {
    __shared__ float s_w2[HH * HH];
    __shared__ float s_b1[HH], s_b2[HH];
    __shared__ float s_z[8][HH];
    int tid = threadIdx.x;
    if (tid < HH * HH) s_w2[tid] = w2[tid];
    if (tid < HH) { s_b1[tid] = b1[tid]; s_b2[tid] = b2[tid]; }
    __syncthreads();
    int warp = tid >> 5, lane = tid & 31;
    int n = blockIdx.x * 8 + warp;   // grid = NN/8 exactly

    const __half* zin  = (pass & 1) ? g_zha : g_zhb;
    __half*       zout = (pass & 1) ? g_zhb : g_zha;
    float*        rout = g_r + (size_t)pass * (size_t)NN * HH;

    int deg = min(g_cursor[n], CAP);
    const int* cp = g_csr2 + n * CAP;
    int eg = lane >> 1;   // edge slot 0..15 per iteration
    int c  = lane & 1;    // half-row: features [c*8, c*8+8)

    float acc[8];
    #pragma unroll
    for (int i = 0; i < 8; i++) acc[i] = 0.f;

    int niter = deg >> 4;
    for (int it = 0; it < niter; it++) {
        int s = cp[it * 16 + eg];
        uint4 u = *(const uint4*)(zin + (size_t)s * HH + c * 8);
        float2 f0 = unpack_h2(u.x);
        float2 f1 = unpack_h2(u.y);
        float2 f2 = unpack_h2(u.z);
        float2 f3 = unpack_h2(u.w);
        acc[0] += f0.x; acc[1] += f0.y; acc[2] += f1.x; acc[3] += f1.y;
        acc[4] += f2.x; acc[5] += f2.y; acc[6] += f3.x; acc[7] += f3.y;
    }
    int rem = deg & 15;
    if (eg < rem) {
        int s = cp[niter * 16 + eg];
        uint4 u = *(const uint4*)(zin + (size_t)s * HH + c * 8);
        float2 f0 = unpack_h2(u.x);
        float2 f1 = unpack_h2(u.y);
        float2 f2 = unpack_h2(u.z);
        float2 f3 = unpack_h2(u.w);
        acc[0] += f0.x; acc[1] += f0.y; acc[2] += f1.x; acc[3] += f1.y;
        acc[4] += f2.x; acc[5] += f2.y; acc[6] += f3.x; acc[7] += f3.y;
    }
    // reduce across the 16 edge slots (lanes with same bit0)
    #pragma unroll
    for (int off = 2; off < 32; off <<= 1) {
        #pragma unroll
        for (int i = 0; i < 8; i++)
            acc[i] += __shfl_xor_sync(0xffffffffu, acc[i], off);
    }
    float inv = (deg > 0) ? 1.f / (float)deg : 0.f;
    #pragma unroll
    for (int i = 0; i < 8; i++) acc[i] *= inv;

    if (lane < 2) {   // lane == c: holds features [lane*8, lane*8+8)
        if (pass != 7) store_half8(zout + (size_t)n * HH + lane * 8, acc);
        #pragma unroll
        for (int i = 0; i < 8; i++) s_z[warp][lane * 8 + i] = acc[i];
    }
    __syncwarp();

    // fused relu2 epilogue (fp32)
    int f = lane & 15;
    float z = s_z[warp][f];
    float h1 = fmaxf(z + s_b1[f], 0.f);
    float h2 = s_b2[f];
    #pragma unroll
    for (int k = 0; k < HH; k++) h2 += __shfl_sync(0xffffffffu, h1, k) * s_w2[k * HH + f];
    h2 = fmaxf(h2, 0.f);
    if (lane < HH) rout[(size_t)n * HH + f] = h2;
}

// ---------------- final head: logits = bias + sum_i relu2_i @ G_i ; softmax --------
__global__ void __launch_bounds__(256) k_final(float* __restrict__ out) {
    __shared__ float sG[NFIELD * HH * AA];
    __shared__ float sB[AA];
    int tid = threadIdx.x;
    for (int i = tid; i < NFIELD * HH * AA; i += 256) sG[i] = g_G[i];
    if (tid < AA) sB[tid] = g_bias[tid];
    __syncthreads();
    int n = blockIdx.x * 256 + tid;
    if (n >= NN) return;

    float acc[AA];
    #pragma unroll
    for (int a = 0; a < AA; a++) acc[a] = sB[a];

    #pragma unroll
    for (int i = 0; i < NFIELD; i++) {
        const float4* rp = (const float4*)(g_r + (size_t)i * (size_t)NN * HH + (size_t)n * HH);
        const float* Gp = sG + i * HH * AA;
        #pragma unroll
        for (int v4 = 0; v4 < 4; v4++) {
            float4 q = rp[v4];
            const float* Gq = Gp + v4 * 4 * AA;
            #pragma unroll
            for (int a = 0; a < AA; a++)
                acc[a] += q.x * Gq[0 * AA + a] + q.y * Gq[1 * AA + a]
                        + q.z * Gq[2 * AA + a] + q.w * Gq[3 * AA + a];
        }
    }

    float mx = acc[0];
    #pragma unroll
    for (int a = 1; a < AA; a++) mx = fmaxf(mx, acc[a]);
    float sum = 0.f;
    #pragma unroll
    for (int a = 0; a < AA; a++) { acc[a] = __expf(acc[a] - mx); sum += acc[a]; }
    float inv = 1.f / sum;
    #pragma unroll
    for (int a = 0; a < AA; a++) out[(size_t)n * AA + a] = acc[a] * inv;
}

// ---------------- launch ----------------
extern "C" void kernel_launch(void* const* d_in, const int* in_sizes, int n_in,
                              void* d_out, int out_size) {
    const float* x    = (const float*)d_in[0];
    const int*   ei   = (const int*)d_in[1];   // int32 words; dtype auto-detected on device
    const float* w1   = (const float*)d_in[2];
    const float* b1   = (const float*)d_in[3];
    const float* w2   = (const float*)d_in[4];
    const float* b2   = (const float*)d_in[5];
    const float* w3   = (const float*)d_in[6];
    const float* b3   = (const float*)d_in[7];
    const float* fc1w = (const float*)d_in[8];
    const float* fc1b = (const float*)d_in[9];
    const float* fc2w = (const float*)d_in[10];
    const float* fc2b = (const float*)d_in[11];
    float* out = (float*)d_out;

    k_pre<<<1, 512>>>(w1, b1, w3, b3, fc1w, fc1b, fc2w, fc2b);
    k_zero<<<(NN + 255) / 256, 256>>>();
    k_detect<<<16, 256>>>(ei);
    k_fill<<<(EE / 4 + 255) / 256, 256>>>(ei);
    k_front<<<NN / 8, 256>>>(x, w1, b1, w2, b2);
    for (int p = 1; p <= 7; p++) {
        k_agg<<<NN / 8, 256>>>(p, b1, w2, b2);
    }
    k_final<<<(NN + 255) / 256, 256>>>(out);
}

// round 15
// speedup vs baseline: 1.7432x; 1.4602x over previous
#include <cuda_runtime.h>
#include <math.h>

#define NN 50000
#define FF 64
#define EE 1600000
#define HH 16
#define AA 8
#define NFIELD 8   /* 1 + RECEPTIVE_FIELD */
#define CAP 128    /* per-node CSR capacity; max in-degree ~60 for this graph */

// ---------------- static device scratch ----------------
__device__ __align__(16) int   g_cursor[NN];
__device__ __align__(16) int   g_csr2[NN * CAP];      // fixed-capacity CSR (cursor = degree)
__device__ __align__(16) float g_za[NN * HH];         // ping
__device__ __align__(16) float g_zb[NN * HH];         // pong
__device__ __align__(16) float g_r[NFIELD * NN * HH]; // relu2 hidden per field
__device__ __align__(16) float g_W31[HH * HH];        // w3 @ w1
__device__ __align__(16) float g_b31[HH];             // b3 @ w1
__device__ __align__(16) float g_T[NFIELD * FF * AA]; // fc1_w @ fc2_w
__device__ __align__(16) float g_G[NFIELD * HH * AA]; // w3 @ fc1_blk_i @ fc2_w
__device__ __align__(16) float g_bias[AA];            // folded logit bias
__device__ int g_odd_nonzero;                         // dtype detection scratch

// ---------------- folded weights precompute ----------------
__global__ void k_pre(const float* __restrict__ w1, const float* __restrict__ b1,
                      const float* __restrict__ w3, const float* __restrict__ b3,
                      const float* __restrict__ fc1w, const float* __restrict__ fc1b,
                      const float* __restrict__ fc2w, const float* __restrict__ fc2b) {
    int t = threadIdx.x;  // 512 threads, 1 block
    if (t < HH * HH) {
        int k = t >> 4, j = t & 15;
        float s = 0.f;
        for (int f = 0; f < FF; f++) s += w3[k * FF + f] * w1[f * HH + j];
        g_W31[t] = s;
    }
    if (t < HH) {
        float s = 0.f;
        for (int f = 0; f < FF; f++) s += b3[f] * w1[f * HH + t];
        g_b31[t] = s;
    }
    {
        float s[AA];
        #pragma unroll
        for (int a = 0; a < AA; a++) s[a] = 0.f;
        for (int k = 0; k < FF; k++) {
            float v = fc1w[t * FF + k];
            #pragma unroll
            for (int a = 0; a < AA; a++) s[a] += v * fc2w[k * AA + a];
        }
        #pragma unroll
        for (int a = 0; a < AA; a++) g_T[t * AA + a] = s[a];
    }
    __syncthreads();
    if (t < NFIELD * HH) {
        int i = t >> 4, j = t & 15;
        float s[AA];
        #pragma unroll
        for (int a = 0; a < AA; a++) s[a] = 0.f;
        for (int f = 0; f < FF; f++) {
            float v = w3[j * FF + f];
            #pragma unroll
            for (int a = 0; a < AA; a++) s[a] += v * g_T[(i * FF + f) * AA + a];
        }
        #pragma unroll
        for (int a = 0; a < AA; a++) g_G[t * AA + a] = s[a];
    }
    if (t < AA) {
        float s = fc2b[t];
        for (int k = 0; k < FF; k++) s += fc1b[k] * fc2w[k * AA + t];
        for (int q = 0; q < NFIELD * FF; q++) s += b3[q & (FF - 1)] * g_T[q * AA + t];
        g_bias[t] = s;
    }
}

// ---------------- CSR build (no hist/scan: fixed-capacity rows) ----------------
__global__ void k_zero() {
    int i = blockIdx.x * 256 + threadIdx.x;
    if (i < NN) g_cursor[i] = 0;
    if (i == 0) g_odd_nonzero = 0;
}

__global__ void k_detect(const int* __restrict__ w) {
    int t = blockIdx.x * 256 + threadIdx.x;   // 4096 threads
    long long i = (long long)t * (EE / 4096);
    if (w[2 * i + 1] != 0) atomicOr(&g_odd_nonzero, 1);
}

__global__ void k_fill(const int* __restrict__ w) {
    int q = blockIdx.x * 256 + threadIdx.x;
    if (q >= EE / 4) return;
    int is64 = (g_odd_nonzero == 0);
    int s[4], d[4];
    if (!is64) {
        int4 s4 = *(const int4*)(w + q * 4);
        int4 d4 = *(const int4*)(w + EE + q * 4);
        s[0] = s4.x; s[1] = s4.y; s[2] = s4.z; s[3] = s4.w;
        d[0] = d4.x; d[1] = d4.y; d[2] = d4.z; d[3] = d4.w;
    } else {
        #pragma unroll
        for (int j = 0; j < 4; j++) {
            s[j] = w[2 * (q * 4 + j)];
            d[j] = w[2 * (long long)EE + 2 * (q * 4 + j)];
        }
    }
    #pragma unroll
    for (int j = 0; j < 4; j++) {
        if ((unsigned)d[j] < (unsigned)NN && (unsigned)s[j] < (unsigned)NN) {
            int p = atomicAdd(&g_cursor[d[j]], 1);
            if (p < CAP) g_csr2[d[j] * CAP + p] = s[j];
        }
    }
}

// ---------------- front: x -> z0 = (mlp(x)) @ w1, and relu2_0 ----------------
__global__ void __launch_bounds__(256) k_front(const float* __restrict__ x,
                                               const float* __restrict__ w1, const float* __restrict__ b1,
                                               const float* __restrict__ w2, const float* __restrict__ b2) {
    __shared__ float s_w1[FF * HH];
    __shared__ float s_w2[HH * HH];
    __shared__ float s_W31[HH * HH];
    __shared__ float s_b1[HH], s_b2[HH], s_b31[HH];
    __shared__ float s_x[8][FF];
    int tid = threadIdx.x;
    for (int i = tid; i < FF * HH; i += 256) s_w1[i] = w1[i];
    if (tid < HH * HH) { s_w2[tid] = w2[tid]; s_W31[tid] = g_W31[tid]; }
    if (tid < HH) { s_b1[tid] = b1[tid]; s_b2[tid] = b2[tid]; s_b31[tid] = g_b31[tid]; }
    __syncthreads();
    int warp = tid >> 5, lane = tid & 31;
    int n = blockIdx.x * 8 + warp;   // grid = NN/8 exactly

    s_x[warp][lane]      = x[n * FF + lane];
    s_x[warp][lane + 32] = x[n * FF + lane + 32];
    __syncwarp();

    int j = lane & 15;
    float h1 = s_b1[j];
    #pragma unroll 16
    for (int f = 0; f < FF; f++) h1 += s_x[warp][f] * s_w1[f * HH + j];
    h1 = fmaxf(h1, 0.f);
    float h2 = s_b2[j];
    #pragma unroll
    for (int k = 0; k < HH; k++) h2 += __shfl_sync(0xffffffffu, h1, k) * s_w2[k * HH + j];
    h2 = fmaxf(h2, 0.f);
    float z = s_b31[j];
    #pragma unroll
    for (int k = 0; k < HH; k++) z += __shfl_sync(0xffffffffu, h2, k) * s_W31[k * HH + j];
    if (lane < HH) g_za[n * HH + j] = z;
    float h1b = fmaxf(z + s_b1[j], 0.f);
    float h2b = s_b2[j];
    #pragma unroll
    for (int k = 0; k < HH; k++) h2b += __shfl_sync(0xffffffffu, h1b, k) * s_w2[k * HH + j];
    h2b = fmaxf(h2b, 0.f);
    if (lane < HH) g_r[n * HH + j] = h2b;
}

// ---------------- agg: 8 edges per warp-iteration via float4 gather ----------------
__global__ void __launch_bounds__(256) k_agg(int pass,
                                             const float* __restrict__ b1,
                                             const float* __restrict__ w2,
                                             const float* __restrict__ b2) {
    __shared__ float s_w2[HH * HH];
    __shared__ float s_b1[HH], s_b2[HH];
    __shared__ float s_z[8][HH];
    int tid = threadIdx.x;
    if (tid < HH * HH) s_w2[tid] = w2[tid];
    if (tid < HH) { s_b1[tid] = b1[tid]; s_b2[tid] = b2[tid]; }
    __syncthreads();
    int warp = tid >> 5, lane = tid & 31;
    int n = blockIdx.x * 8 + warp;   // grid = NN/8 exactly

    const float* zin  = (pass & 1) ? g_za : g_zb;
    float*       zout = (pass & 1) ? g_zb : g_za;
    float*       rout = g_r + (size_t)pass * (size_t)NN * HH;

    int deg = min(g_cursor[n], CAP);
    const int* cp = g_csr2 + n * CAP;
    int eg = lane >> 2;   // edge slot 0..7
    int c4 = lane & 3;    // float4 column

    float4 acc = make_float4(0.f, 0.f, 0.f, 0.f);
    int noct = deg >> 3;
    int it = 0;
    for (; it + 2 <= noct; it += 2) {
        int s0 = cp[it * 8 + eg];
        int s1 = cp[it * 8 + 8 + eg];
        float4 v0 = *(const float4*)(zin + s0 * HH + c4 * 4);
        float4 v1 = *(const float4*)(zin + s1 * HH + c4 * 4);
        acc.x += v0.x + v1.x; acc.y += v0.y + v1.y;
        acc.z += v0.z + v1.z; acc.w += v0.w + v1.w;
    }
    for (; it < noct; it++) {
        int s = cp[it * 8 + eg];
        float4 v = *(const float4*)(zin + s * HH + c4 * 4);
        acc.x += v.x; acc.y += v.y; acc.z += v.z; acc.w += v.w;
    }
    int trem = deg & 7;
    if (eg < trem) {
        int s = cp[noct * 8 + eg];
        float4 v = *(const float4*)(zin + s * HH + c4 * 4);
        acc.x += v.x; acc.y += v.y; acc.z += v.z; acc.w += v.w;
    }
    #pragma unroll
    for (int off = 4; off < 32; off <<= 1) {
        acc.x += __shfl_xor_sync(0xffffffffu, acc.x, off);
        acc.y += __shfl_xor_sync(0xffffffffu, acc.y, off);
        acc.z += __shfl_xor_sync(0xffffffffu, acc.z, off);
        acc.w += __shfl_xor_sync(0xffffffffu, acc.w, off);
    }
    float inv = (deg > 0) ? 1.f / (float)deg : 0.f;
    acc.x *= inv; acc.y *= inv; acc.z *= inv; acc.w *= inv;

    if (lane < 4) {   // lane == c4: holds features [lane*4, lane*4+4)
        if (pass != 7) *(float4*)(zout + (size_t)n * HH + lane * 4) = acc;
        s_z[warp][lane * 4 + 0] = acc.x;
        s_z[warp][lane * 4 + 1] = acc.y;
        s_z[warp][lane * 4 + 2] = acc.z;
        s_z[warp][lane * 4 + 3] = acc.w;
    }
    __syncwarp();

    // fused relu2 epilogue
    int f = lane & 15;
    float z = s_z[warp][f];
    float h1 = fmaxf(z + s_b1[f], 0.f);
    float h2 = s_b2[f];
    #pragma unroll
    for (int k = 0; k < HH; k++) h2 += __shfl_sync(0xffffffffu, h1, k) * s_w2[k * HH + f];
    h2 = fmaxf(h2, 0.f);
    if (lane < HH) rout[(size_t)n * HH + f] = h2;
}

// ---------------- final head: logits = bias + sum_i relu2_i @ G_i ; softmax --------
__global__ void __launch_bounds__(256) k_final(float* __restrict__ out) {
    __shared__ float sG[NFIELD * HH * AA];
    __shared__ float sB[AA];
    int tid = threadIdx.x;
    for (int i = tid; i < NFIELD * HH * AA; i += 256) sG[i] = g_G[i];
    if (tid < AA) sB[tid] = g_bias[tid];
    __syncthreads();
    int n = blockIdx.x * 256 + tid;
    if (n >= NN) return;

    float acc[AA];
    #pragma unroll
    for (int a = 0; a < AA; a++) acc[a] = sB[a];

    #pragma unroll
    for (int i = 0; i < NFIELD; i++) {
        const float4* rp = (const float4*)(g_r + (size_t)i * (size_t)NN * HH + (size_t)n * HH);
        const float* Gp = sG + i * HH * AA;
        #pragma unroll
        for (int v4 = 0; v4 < 4; v4++) {
            float4 q = rp[v4];
            const float* Gq = Gp + v4 * 4 * AA;
            #pragma unroll
            for (int a = 0; a < AA; a++)
                acc[a] += q.x * Gq[0 * AA + a] + q.y * Gq[1 * AA + a]
                        + q.z * Gq[2 * AA + a] + q.w * Gq[3 * AA + a];
        }
    }

    float mx = acc[0];
    #pragma unroll
    for (int a = 1; a < AA; a++) mx = fmaxf(mx, acc[a]);
    float sum = 0.f;
    #pragma unroll
    for (int a = 0; a < AA; a++) { acc[a] = __expf(acc[a] - mx); sum += acc[a]; }
    float inv = 1.f / sum;
    #pragma unroll
    for (int a = 0; a < AA; a++) out[(size_t)n * AA + a] = acc[a] * inv;
}

// ---------------- launch ----------------
extern "C" void kernel_launch(void* const* d_in, const int* in_sizes, int n_in,
                              void* d_out, int out_size) {
    const float* x    = (const float*)d_in[0];
    const int*   ei   = (const int*)d_in[1];   // int32 words; dtype auto-detected on device
    const float* w1   = (const float*)d_in[2];
    const float* b1   = (const float*)d_in[3];
    const float* w2   = (const float*)d_in[4];
    const float* b2   = (const float*)d_in[5];
    const float* w3   = (const float*)d_in[6];
    const float* b3   = (const float*)d_in[7];
    const float* fc1w = (const float*)d_in[8];
    const float* fc1b = (const float*)d_in[9];
    const float* fc2w = (const float*)d_in[10];
    const float* fc2b = (const float*)d_in[11];
    float* out = (float*)d_out;

    k_pre<<<1, 512>>>(w1, b1, w3, b3, fc1w, fc1b, fc2w, fc2b);
    k_zero<<<(NN + 255) / 256, 256>>>();
    k_detect<<<16, 256>>>(ei);
    k_fill<<<(EE / 4 + 255) / 256, 256>>>(ei);
    k_front<<<NN / 8, 256>>>(x, w1, b1, w2, b2);
    for (int p = 1; p <= 7; p++) {
        k_agg<<<NN / 8, 256>>>(p, b1, w2, b2);
    }
    k_final<<<(NN + 255) / 256, 256>>>(out);
}